// round 7
// baseline (speedup 1.0000x reference)
#include <cuda_runtime.h>

#define HID 64
#define GATES 192
#define BATCH 4096
#define TSTEPS 512
#define TILE_B 32
#define NCTA 128
#define NTHREADS 512

typedef unsigned long long ull;

// smem layout (float offsets)
#define OFF_W0   0        // Whh0 packed [k2][pair][blk][gi][kl] (12288)
#define OFF_WA   12288    // Wih1 packed
#define OFF_WB   24576    // Whh1 packed
#define OFF_H0   36864    // h0: 2 buffers x [32][64] swizzled
#define OFF_H1   40960    // h1: 2 buffers
#define OFF_WIH0 45056    // Wih0 col-major [2][192], r/z scaled 0.5
#define OFF_MB0  45440    // 0.5*(bih0+bhh0) r/z [128]
#define OFF_B0NX 45568
#define OFF_B0NH 45632
#define OFF_MB1  45696
#define OFF_B1NA 45824
#define OFF_B1NB 45888
#define OFF_WP   45952
#define OFF_XS   46080    // x staging float2[32]
#define SMEM_FLOATS 46144
#define SMEM_BYTES (SMEM_FLOATS * 4)   // 184576 B

__device__ __forceinline__ ull ffma2(ull a, ull b, ull c) {
    ull d; asm("fma.rn.f32x2 %0, %1, %2, %3;" : "=l"(d) : "l"(a), "l"(b), "l"(c)); return d;
}
__device__ __forceinline__ void unpk(ull v, float& lo, float& hi) {
    asm("mov.b64 {%0, %1}, %2;" : "=f"(lo), "=f"(hi) : "l"(v));
}
__device__ __forceinline__ float tanhx(float v) {
    float y; asm("tanh.approx.f32 %0, %1;" : "=f"(y) : "f"(v)); return y;
}
// swizzle: chunk index XORed with b>>1 (distinct across the 16 lane-groups)
__device__ __forceinline__ int haddr(int b, int j) {
    return b * 64 + ((((j >> 2) ^ (b >> 1)) << 2) | (j & 3));
}
__device__ __forceinline__ int hchunk(int b, int c) {
    return b * 64 + (((c ^ (b >> 1)) & 15) << 2);
}

extern __shared__ float smem[];

__global__ void __launch_bounds__(NTHREADS, 1)
gru2_r7_kernel(const float* __restrict__ x,
               const float* __restrict__ Wih0, const float* __restrict__ Whh0,
               const float* __restrict__ bih0, const float* __restrict__ bhh0,
               const float* __restrict__ Wih1, const float* __restrict__ Whh1,
               const float* __restrict__ bih1, const float* __restrict__ bhh1,
               const float* __restrict__ Wp,   const float* __restrict__ bp,
               float* __restrict__ out)
{
    const int tid = threadIdx.x;
    const int b0  = blockIdx.x * TILE_B;

    float* w0s  = smem + OFF_W0;
    float* was  = smem + OFF_WA;
    float* wbs  = smem + OFF_WB;
    float* h0bs = smem + OFF_H0;
    float* h1bs = smem + OFF_H1;
    float* wih0s = smem + OFF_WIH0;
    float2* xsf = (float2*)(smem + OFF_XS);

    // ---- prologue: pack weights as {w_k, w_k+1} per gate, [k2][pair][blk] ----
    for (int d = tid; d < HID * GATES; d += NTHREADS) {
        int g = d >> 6, k = d & 63;        // source [192][64] row-major
        float s = (g < 128) ? 0.5f : 1.0f;
        int blk = g >> 6, j = g & 63;
        int fpos = (k >> 1) * 384 + (j >> 1) * 12 + blk * 4 + (j & 1) * 2 + (k & 1);
        w0s[fpos] = Whh0[d] * s;
        was[fpos] = Wih1[d] * s;
        wbs[fpos] = Whh1[d] * s;
    }
    for (int g = tid; g < GATES; g += NTHREADS) {
        float s = (g < 128) ? 0.5f : 1.0f;
        wih0s[g]         = Wih0[2 * g]     * s;
        wih0s[GATES + g] = Wih0[2 * g + 1] * s;
    }
    if (tid < 128) {
        smem[OFF_MB0 + tid] = 0.5f * (bih0[tid] + bhh0[tid]);
        smem[OFF_MB1 + tid] = 0.5f * (bih1[tid] + bhh1[tid]);
        smem[OFF_WP + tid]  = Wp[tid];
    }
    if (tid < 64) {
        smem[OFF_B0NX + tid] = bih0[128 + tid];
        smem[OFF_B0NH + tid] = bhh0[128 + tid];
        smem[OFF_B1NA + tid] = bih1[128 + tid];
        smem[OFF_B1NB + tid] = bhh1[128 + tid];
    }
    for (int d = tid; d < 8192; d += NTHREADS) h0bs[d] = 0.0f;   // h0 + h1, both buffers
    if (tid < TILE_B)
        xsf[tid] = *(const float2*)(x + (size_t)(b0 + tid) * 2);
    __syncthreads();

    // thread tiling: pair = gate-pair (j0, j0+1), bg = batch group of 2
    const int pair = tid >> 4;          // 0..31
    const int bg   = tid & 15;          // 0..15
    const int j0   = pair * 2;
    const int bb   = bg * 2;

    // persistent per-thread constants
    float mb0r[2], mb0z[2], b0nx_[2], b0nh_[2];
    float mb1r[2], mb1z[2], b1nA_[2], b1nB_[2];
    float xwr0[2], xwr1[2], xwz0[2], xwz1[2], xwn0[2], xwn1[2];
    #pragma unroll
    for (int g = 0; g < 2; ++g) {
        mb0r[g]  = smem[OFF_MB0 + j0 + g];
        mb0z[g]  = smem[OFF_MB0 + 64 + j0 + g];
        b0nx_[g] = smem[OFF_B0NX + j0 + g];
        b0nh_[g] = smem[OFF_B0NH + j0 + g];
        mb1r[g]  = smem[OFF_MB1 + j0 + g];
        mb1z[g]  = smem[OFF_MB1 + 64 + j0 + g];
        b1nA_[g] = smem[OFF_B1NA + j0 + g];
        b1nB_[g] = smem[OFF_B1NB + j0 + g];
        xwr0[g] = wih0s[j0 + g];        xwr1[g] = wih0s[GATES + j0 + g];
        xwz0[g] = wih0s[64 + j0 + g];   xwz1[g] = wih0s[GATES + 64 + j0 + g];
        xwn0[g] = wih0s[128 + j0 + g];  xwn1[g] = wih0s[GATES + 128 + j0 + g];
    }
    // both rows of this thread share the same XOR value: bg = (bb+i)>>1
    int rowb[2];
    #pragma unroll
    for (int i = 0; i < 2; ++i) rowb[i] = (bb + i) * 64;

    const float* wbase0 = w0s + pair * 12;
    const float* wbaseA = was + pair * 12;
    const float* wbaseB = wbs + pair * 12;

    for (int t = 0; t < TSTEPS; ++t) {
        const int p = (t & 1) << 11;
        float* h0r = h0bs + p;
        float* h0w = h0bs + (p ^ 2048);
        float* h1r = h1bs + p;
        float* h1w = h1bs + (p ^ 2048);

        // ============ phase 1: GEMM1 (h0 @ Whh0^T, k-paired) + gates L0 ============
        ull ar[2][2], az[2][2], an[2][2];
        #pragma unroll
        for (int i = 0; i < 2; ++i) {
            ar[0][i] = 0; ar[1][i] = 0; az[0][i] = 0;
            az[1][i] = 0; an[0][i] = 0; an[1][i] = 0;
        }

        #pragma unroll 4
        for (int k4 = 0; k4 < 16; ++k4) {
            const int coff = ((k4 ^ bg) << 2);
            ulonglong2 h[2];
            #pragma unroll
            for (int i = 0; i < 2; ++i)
                h[i] = *(const ulonglong2*)(h0r + rowb[i] + coff);
            #pragma unroll
            for (int kp = 0; kp < 2; ++kp) {
                const float* w = wbase0 + (k4 * 2 + kp) * 384;
                ulonglong2 wr = *(const ulonglong2*)(w);
                ulonglong2 wz = *(const ulonglong2*)(w + 4);
                ulonglong2 wn = *(const ulonglong2*)(w + 8);
                #pragma unroll
                for (int i = 0; i < 2; ++i) {
                    ull hv = kp ? h[i].y : h[i].x;
                    ar[0][i] = ffma2(wr.x, hv, ar[0][i]);
                    ar[1][i] = ffma2(wr.y, hv, ar[1][i]);
                    az[0][i] = ffma2(wz.x, hv, az[0][i]);
                    az[1][i] = ffma2(wz.y, hv, az[1][i]);
                    an[0][i] = ffma2(wn.x, hv, an[0][i]);
                    an[1][i] = ffma2(wn.y, hv, an[1][i]);
                }
            }
        }

        // epilogue L0
        #pragma unroll
        for (int i = 0; i < 2; ++i) {
            int b = bb + i;
            float2 xv = xsf[b];
            float2 hp = *(const float2*)(h0r + haddr(b, j0));
            float o[2];
            #pragma unroll
            for (int g = 0; g < 2; ++g) {
                float rl, rh, zl, zh, nl, nh;
                unpk(ar[g][i], rl, rh);
                unpk(az[g][i], zl, zh);
                unpk(an[g][i], nl, nh);
                float rsum = fmaf(xv.y, xwr1[g], fmaf(xv.x, xwr0[g], (rl + rh) + mb0r[g]));
                float zsum = fmaf(xv.y, xwz1[g], fmaf(xv.x, xwz0[g], (zl + zh) + mb0z[g]));
                float sr = fmaf(tanhx(rsum), 0.5f, 0.5f);
                float sz = fmaf(tanhx(zsum), 0.5f, 0.5f);
                float hn = (nl + nh) + b0nh_[g];
                float xn = fmaf(xv.y, xwn1[g], fmaf(xv.x, xwn0[g], b0nx_[g]));
                float n = tanhx(fmaf(sr, hn, xn));
                float hprev = g ? hp.y : hp.x;
                o[g] = fmaf(sz, hprev - n, n);
            }
            *(float2*)(h0w + haddr(b, j0)) = make_float2(o[0], o[1]);
        }
        __syncthreads();

        // ============ phase 2: GEMM2 (h0new@Wih1 + h1@Whh1) + gates L1 ============
        float2 xnext = make_float2(0.0f, 0.0f);
        if (tid < TILE_B && t + 1 < TSTEPS)
            xnext = *(const float2*)(x + ((size_t)(t + 1) * BATCH + b0 + tid) * 2);

        ull cr[2][2], cz[2][2], cA[2][2], cB[2][2];
        #pragma unroll
        for (int i = 0; i < 2; ++i) {
            cr[0][i] = 0; cr[1][i] = 0; cz[0][i] = 0; cz[1][i] = 0;
            cA[0][i] = 0; cA[1][i] = 0; cB[0][i] = 0; cB[1][i] = 0;
        }

        #pragma unroll 4
        for (int k4 = 0; k4 < 16; ++k4) {
            const int coff = ((k4 ^ bg) << 2);
            ulonglong2 hA[2], hB[2];
            #pragma unroll
            for (int i = 0; i < 2; ++i) {
                int off = rowb[i] + coff;
                hA[i] = *(const ulonglong2*)(h0w + off);
                hB[i] = *(const ulonglong2*)(h1r + off);
            }
            #pragma unroll
            for (int kp = 0; kp < 2; ++kp) {
                int woff = (k4 * 2 + kp) * 384;
                const float* wa = wbaseA + woff;
                const float* wb = wbaseB + woff;
                ulonglong2 war = *(const ulonglong2*)(wa);
                ulonglong2 waz = *(const ulonglong2*)(wa + 4);
                ulonglong2 wan = *(const ulonglong2*)(wa + 8);
                ulonglong2 wbr = *(const ulonglong2*)(wb);
                ulonglong2 wbz = *(const ulonglong2*)(wb + 4);
                ulonglong2 wbn = *(const ulonglong2*)(wb + 8);
                #pragma unroll
                for (int i = 0; i < 2; ++i) {
                    ull av = kp ? hA[i].y : hA[i].x;
                    ull bv = kp ? hB[i].y : hB[i].x;
                    cr[0][i] = ffma2(war.x, av, cr[0][i]);
                    cr[0][i] = ffma2(wbr.x, bv, cr[0][i]);
                    cr[1][i] = ffma2(war.y, av, cr[1][i]);
                    cr[1][i] = ffma2(wbr.y, bv, cr[1][i]);
                    cz[0][i] = ffma2(waz.x, av, cz[0][i]);
                    cz[0][i] = ffma2(wbz.x, bv, cz[0][i]);
                    cz[1][i] = ffma2(waz.y, av, cz[1][i]);
                    cz[1][i] = ffma2(wbz.y, bv, cz[1][i]);
                    cA[0][i] = ffma2(wan.x, av, cA[0][i]);
                    cA[1][i] = ffma2(wan.y, av, cA[1][i]);
                    cB[0][i] = ffma2(wbn.x, bv, cB[0][i]);
                    cB[1][i] = ffma2(wbn.y, bv, cB[1][i]);
                }
            }
        }

        if (tid < TILE_B) xsf[tid] = xnext;

        // epilogue L1
        #pragma unroll
        for (int i = 0; i < 2; ++i) {
            int b = bb + i;
            float2 hp = *(const float2*)(h1r + haddr(b, j0));
            float o[2];
            #pragma unroll
            for (int g = 0; g < 2; ++g) {
                float rl, rh, zl, zh, al, ah, bl, bh;
                unpk(cr[g][i], rl, rh);
                unpk(cz[g][i], zl, zh);
                unpk(cA[g][i], al, ah);
                unpk(cB[g][i], bl, bh);
                float sr = fmaf(tanhx((rl + rh) + mb1r[g]), 0.5f, 0.5f);
                float sz = fmaf(tanhx((zl + zh) + mb1z[g]), 0.5f, 0.5f);
                float xn = (al + ah) + b1nA_[g];
                float hn = (bl + bh) + b1nB_[g];
                float n = tanhx(fmaf(sr, hn, xn));
                float hprev = g ? hp.y : hp.x;
                o[g] = fmaf(sz, hprev - n, n);
            }
            *(float2*)(h1w + haddr(b, j0)) = make_float2(o[0], o[1]);
        }
        __syncthreads();
    }

    // ---- final projection (final states in buffer 0: TSTEPS even) ----
    if (tid < TILE_B) {
        int b = tid;
        const float* wps = smem + OFF_WP;
        float s = bp[0];
        #pragma unroll
        for (int c = 0; c < 16; ++c) {
            float4 h4 = *(const float4*)(h0bs + hchunk(b, c));
            int k = c * 4;
            s = fmaf(h4.x, wps[k], s);
            s = fmaf(h4.y, wps[k + 1], s);
            s = fmaf(h4.z, wps[k + 2], s);
            s = fmaf(h4.w, wps[k + 3], s);
        }
        #pragma unroll
        for (int c = 0; c < 16; ++c) {
            float4 h4 = *(const float4*)(h1bs + hchunk(b, c));
            int k = 64 + c * 4;
            s = fmaf(h4.x, wps[k], s);
            s = fmaf(h4.y, wps[k + 1], s);
            s = fmaf(h4.z, wps[k + 2], s);
            s = fmaf(h4.w, wps[k + 3], s);
        }
        out[b0 + tid] = s;
    }
}

extern "C" void kernel_launch(void* const* d_in, const int* in_sizes, int n_in,
                              void* d_out, int out_size) {
    const float* x    = (const float*)d_in[0];
    const float* Wih0 = (const float*)d_in[1];
    const float* Whh0 = (const float*)d_in[2];
    const float* bih0 = (const float*)d_in[3];
    const float* bhh0 = (const float*)d_in[4];
    const float* Wih1 = (const float*)d_in[5];
    const float* Whh1 = (const float*)d_in[6];
    const float* bih1 = (const float*)d_in[7];
    const float* bhh1 = (const float*)d_in[8];
    const float* Wp   = (const float*)d_in[9];
    const float* bp   = (const float*)d_in[10];
    float* out = (float*)d_out;

    cudaFuncSetAttribute(gru2_r7_kernel,
                         cudaFuncAttributeMaxDynamicSharedMemorySize, SMEM_BYTES);
    gru2_r7_kernel<<<NCTA, NTHREADS, SMEM_BYTES>>>(
        x, Wih0, Whh0, bih0, bhh0, Wih1, Whh1, bih1, bhh1, Wp, bp, out);
}

// round 8
// speedup vs baseline: 1.1570x; 1.1570x over previous
#include <cuda_runtime.h>

#define HID 64
#define GATES 192
#define BATCH 4096
#define TSTEPS 512
#define TILE_B 32
#define NCTA 128
#define NTHREADS 512

typedef unsigned long long ull;

// smem layout (float offsets)
#define OFF_W0   0        // Whh0 packed [k2][pair][blk][gi][kl] (12288)
#define OFF_WA   12288    // Wih1 packed
#define OFF_WB   24576    // Whh1 packed
#define OFF_H0   36864    // h0: 2 buffers x [32][64] swizzled
#define OFF_H1   40960    // h1: 2 buffers
#define OFF_WIH0 45056    // Wih0 col-major [2][192], r/z scaled 0.5
#define OFF_MB0  45440    // 0.5*(bih0+bhh0) r/z [128]
#define OFF_B0NX 45568
#define OFF_B0NH 45632
#define OFF_MB1  45696
#define OFF_B1NA 45824
#define OFF_B1NB 45888
#define OFF_WP   45952
#define OFF_XS   46080    // x staging float2[2][32]
#define SMEM_FLOATS 46208
#define SMEM_BYTES (SMEM_FLOATS * 4)   // 184832 B

__device__ __forceinline__ ull ffma2(ull a, ull b, ull c) {
    ull d; asm("fma.rn.f32x2 %0, %1, %2, %3;" : "=l"(d) : "l"(a), "l"(b), "l"(c)); return d;
}
__device__ __forceinline__ void unpk(ull v, float& lo, float& hi) {
    asm("mov.b64 {%0, %1}, %2;" : "=f"(lo), "=f"(hi) : "l"(v));
}
__device__ __forceinline__ float tanhx(float v) {
    float y; asm("tanh.approx.f32 %0, %1;" : "=f"(y) : "f"(v)); return y;
}
// swizzle: chunk index XORed with b>>2 (distinct across 8 lane-groups)
__device__ __forceinline__ int haddr(int b, int j) {
    return b * 64 + ((((j >> 2) ^ (b >> 2)) << 2) | (j & 3));
}
__device__ __forceinline__ int hchunk(int b, int c) {
    return b * 64 + (((c ^ (b >> 2)) & 15) << 2);
}

extern __shared__ float smem[];

__global__ void __launch_bounds__(NTHREADS, 1)
gru2_r8_kernel(const float* __restrict__ x,
               const float* __restrict__ Wih0, const float* __restrict__ Whh0,
               const float* __restrict__ bih0, const float* __restrict__ bhh0,
               const float* __restrict__ Wih1, const float* __restrict__ Whh1,
               const float* __restrict__ bih1, const float* __restrict__ bhh1,
               const float* __restrict__ Wp,   const float* __restrict__ bp,
               float* __restrict__ out)
{
    const int tid = threadIdx.x;
    const int b0  = blockIdx.x * TILE_B;

    float* w0s  = smem + OFF_W0;
    float* was  = smem + OFF_WA;
    float* wbs  = smem + OFF_WB;
    float* h0bs = smem + OFF_H0;
    float* h1bs = smem + OFF_H1;
    float* wih0s = smem + OFF_WIH0;
    float2* xsf = (float2*)(smem + OFF_XS);

    // ---- prologue: pack weights as {w_k, w_k+1} per gate, [k2][pair][blk] ----
    for (int d = tid; d < HID * GATES; d += NTHREADS) {
        int g = d >> 6, k = d & 63;        // source [192][64] row-major
        float s = (g < 128) ? 0.5f : 1.0f;
        int blk = g >> 6, j = g & 63;
        int fpos = (k >> 1) * 384 + (j >> 1) * 12 + blk * 4 + (j & 1) * 2 + (k & 1);
        w0s[fpos] = Whh0[d] * s;
        was[fpos] = Wih1[d] * s;
        wbs[fpos] = Whh1[d] * s;
    }
    for (int g = tid; g < GATES; g += NTHREADS) {
        float s = (g < 128) ? 0.5f : 1.0f;
        wih0s[g]         = Wih0[2 * g]     * s;
        wih0s[GATES + g] = Wih0[2 * g + 1] * s;
    }
    if (tid < 128) {
        smem[OFF_MB0 + tid] = 0.5f * (bih0[tid] + bhh0[tid]);
        smem[OFF_MB1 + tid] = 0.5f * (bih1[tid] + bhh1[tid]);
        smem[OFF_WP + tid]  = Wp[tid];
    }
    if (tid < 64) {
        smem[OFF_B0NX + tid] = bih0[128 + tid];
        smem[OFF_B0NH + tid] = bhh0[128 + tid];
        smem[OFF_B1NA + tid] = bih1[128 + tid];
        smem[OFF_B1NB + tid] = bhh1[128 + tid];
    }
    for (int d = tid; d < 8192; d += NTHREADS) h0bs[d] = 0.0f;   // h0 + h1, both buffers
    if (tid < TILE_B)
        xsf[tid] = *(const float2*)(x + (size_t)(b0 + tid) * 2);   // x(0) -> slot 0
    __syncthreads();

    // tiling within each 256-thread group: pair = gate-pair, bg = batch group of 4
    const int gtid = tid & 255;
    const int pair = gtid >> 3;         // 0..31
    const int bg   = gtid & 7;          // 0..7
    const int j0   = pair * 2;
    const int bb   = bg * 4;

    int rowb[4];
    #pragma unroll
    for (int i = 0; i < 4; ++i) rowb[i] = (bb + i) * 64;

    const float* wbase0 = w0s + pair * 12;
    const float* wbaseA = was + pair * 12;
    const float* wbaseB = wbs + pair * 12;

    // pipeline: iteration i -> group A does L0 step t=i, group B does L1 step t=i-1
    for (int it = 0; it <= TSTEPS; ++it) {
        if (tid < 256) {
            if (it < TSTEPS) {
                // ======== group A: GEMM1 (h0 @ Whh0^T) + gates L0, step t=it ========
                const float* h0r = h0bs + (((it + 1) & 1) << 11);
                float* h0w       = h0bs + ((it & 1) << 11);

                float2 xnext = make_float2(0.0f, 0.0f);
                if (gtid < TILE_B && it + 1 < TSTEPS)
                    xnext = *(const float2*)(x + ((size_t)(it + 1) * BATCH + b0 + gtid) * 2);

                ull ar[2][4], az[2][4], an[2][4];
                #pragma unroll
                for (int i = 0; i < 4; ++i) {
                    ar[0][i] = 0; ar[1][i] = 0; az[0][i] = 0;
                    az[1][i] = 0; an[0][i] = 0; an[1][i] = 0;
                }

                #pragma unroll 4
                for (int k4 = 0; k4 < 16; ++k4) {
                    const int coff = ((k4 ^ bg) << 2);
                    ulonglong2 h[4];
                    #pragma unroll
                    for (int i = 0; i < 4; ++i)
                        h[i] = *(const ulonglong2*)(h0r + rowb[i] + coff);
                    #pragma unroll
                    for (int kp = 0; kp < 2; ++kp) {
                        const float* w = wbase0 + (k4 * 2 + kp) * 384;
                        ulonglong2 wr = *(const ulonglong2*)(w);
                        ulonglong2 wz = *(const ulonglong2*)(w + 4);
                        ulonglong2 wn = *(const ulonglong2*)(w + 8);
                        #pragma unroll
                        for (int i = 0; i < 4; ++i) {
                            ull hv = kp ? h[i].y : h[i].x;
                            ar[0][i] = ffma2(wr.x, hv, ar[0][i]);
                            ar[1][i] = ffma2(wr.y, hv, ar[1][i]);
                            az[0][i] = ffma2(wz.x, hv, az[0][i]);
                            az[1][i] = ffma2(wz.y, hv, az[1][i]);
                            an[0][i] = ffma2(wn.x, hv, an[0][i]);
                            an[1][i] = ffma2(wn.y, hv, an[1][i]);
                        }
                    }
                }

                // constants reloaded per step (register relief at 512 threads)
                float2 mb0r2 = *(const float2*)(smem + OFF_MB0 + j0);
                float2 mb0z2 = *(const float2*)(smem + OFF_MB0 + 64 + j0);
                float2 b0nx2 = *(const float2*)(smem + OFF_B0NX + j0);
                float2 b0nh2 = *(const float2*)(smem + OFF_B0NH + j0);
                float2 xwr0 = *(const float2*)(wih0s + j0);
                float2 xwz0 = *(const float2*)(wih0s + 64 + j0);
                float2 xwn0 = *(const float2*)(wih0s + 128 + j0);
                float2 xwr1 = *(const float2*)(wih0s + GATES + j0);
                float2 xwz1 = *(const float2*)(wih0s + GATES + 64 + j0);
                float2 xwn1 = *(const float2*)(wih0s + GATES + 128 + j0);

                #pragma unroll
                for (int i = 0; i < 4; ++i) {
                    int b = bb + i;
                    float2 xv = xsf[(it & 1) * TILE_B + b];
                    float2 hp = *(const float2*)(h0r + haddr(b, j0));
                    float o[2];
                    #pragma unroll
                    for (int g = 0; g < 2; ++g) {
                        float rl, rh, zl, zh, nl, nh;
                        unpk(ar[g][i], rl, rh);
                        unpk(az[g][i], zl, zh);
                        unpk(an[g][i], nl, nh);
                        float mbr = g ? mb0r2.y : mb0r2.x;
                        float mbz = g ? mb0z2.y : mb0z2.x;
                        float bnx = g ? b0nx2.y : b0nx2.x;
                        float bnh = g ? b0nh2.y : b0nh2.x;
                        float wr0 = g ? xwr0.y : xwr0.x, wr1 = g ? xwr1.y : xwr1.x;
                        float wz0 = g ? xwz0.y : xwz0.x, wz1 = g ? xwz1.y : xwz1.x;
                        float wn0 = g ? xwn0.y : xwn0.x, wn1 = g ? xwn1.y : xwn1.x;
                        float rsum = fmaf(xv.y, wr1, fmaf(xv.x, wr0, (rl + rh) + mbr));
                        float zsum = fmaf(xv.y, wz1, fmaf(xv.x, wz0, (zl + zh) + mbz));
                        float sr = fmaf(tanhx(rsum), 0.5f, 0.5f);
                        float sz = fmaf(tanhx(zsum), 0.5f, 0.5f);
                        float hn = (nl + nh) + bnh;
                        float xn = fmaf(xv.y, wn1, fmaf(xv.x, wn0, bnx));
                        float n = tanhx(fmaf(sr, hn, xn));
                        float hprev = g ? hp.y : hp.x;
                        o[g] = fmaf(sz, hprev - n, n);
                    }
                    *(float2*)(h0w + haddr(b, j0)) = make_float2(o[0], o[1]);
                }

                if (gtid < TILE_B)
                    xsf[((it + 1) & 1) * TILE_B + gtid] = xnext;
            }
        } else {
            if (it >= 1) {
                // ======== group B: GEMM2 (h0@Wih1 + h1@Whh1) + gates L1, step t=it-1 ========
                const float* hAr = h0bs + (((it - 1) & 1) << 11);   // h0 after t=it-1
                const float* h1r = h1bs + ((it & 1) << 11);         // h1 after t=it-2
                float* h1w       = h1bs + (((it - 1) & 1) << 11);

                ull cr[2][4], cz[2][4], cA[2][4], cB[2][4];
                #pragma unroll
                for (int i = 0; i < 4; ++i) {
                    cr[0][i] = 0; cr[1][i] = 0; cz[0][i] = 0; cz[1][i] = 0;
                    cA[0][i] = 0; cA[1][i] = 0; cB[0][i] = 0; cB[1][i] = 0;
                }

                #pragma unroll 2
                for (int k4 = 0; k4 < 16; ++k4) {
                    const int coff = ((k4 ^ bg) << 2);
                    ulonglong2 hA[4], hB[4];
                    #pragma unroll
                    for (int i = 0; i < 4; ++i) {
                        int off = rowb[i] + coff;
                        hA[i] = *(const ulonglong2*)(hAr + off);
                        hB[i] = *(const ulonglong2*)(h1r + off);
                    }
                    #pragma unroll
                    for (int kp = 0; kp < 2; ++kp) {
                        int woff = (k4 * 2 + kp) * 384;
                        const float* wa = wbaseA + woff;
                        const float* wb = wbaseB + woff;
                        ulonglong2 war = *(const ulonglong2*)(wa);
                        ulonglong2 waz = *(const ulonglong2*)(wa + 4);
                        ulonglong2 wan = *(const ulonglong2*)(wa + 8);
                        ulonglong2 wbr = *(const ulonglong2*)(wb);
                        ulonglong2 wbz = *(const ulonglong2*)(wb + 4);
                        ulonglong2 wbn = *(const ulonglong2*)(wb + 8);
                        #pragma unroll
                        for (int i = 0; i < 4; ++i) {
                            ull av = kp ? hA[i].y : hA[i].x;
                            ull bv = kp ? hB[i].y : hB[i].x;
                            cr[0][i] = ffma2(war.x, av, cr[0][i]);
                            cr[0][i] = ffma2(wbr.x, bv, cr[0][i]);
                            cr[1][i] = ffma2(war.y, av, cr[1][i]);
                            cr[1][i] = ffma2(wbr.y, bv, cr[1][i]);
                            cz[0][i] = ffma2(waz.x, av, cz[0][i]);
                            cz[0][i] = ffma2(wbz.x, bv, cz[0][i]);
                            cz[1][i] = ffma2(waz.y, av, cz[1][i]);
                            cz[1][i] = ffma2(wbz.y, bv, cz[1][i]);
                            cA[0][i] = ffma2(wan.x, av, cA[0][i]);
                            cA[1][i] = ffma2(wan.y, av, cA[1][i]);
                            cB[0][i] = ffma2(wbn.x, bv, cB[0][i]);
                            cB[1][i] = ffma2(wbn.y, bv, cB[1][i]);
                        }
                    }
                }

                float2 mb1r2 = *(const float2*)(smem + OFF_MB1 + j0);
                float2 mb1z2 = *(const float2*)(smem + OFF_MB1 + 64 + j0);
                float2 b1nA2 = *(const float2*)(smem + OFF_B1NA + j0);
                float2 b1nB2 = *(const float2*)(smem + OFF_B1NB + j0);

                #pragma unroll
                for (int i = 0; i < 4; ++i) {
                    int b = bb + i;
                    float2 hp = *(const float2*)(h1r + haddr(b, j0));
                    float o[2];
                    #pragma unroll
                    for (int g = 0; g < 2; ++g) {
                        float rl, rh, zl, zh, al, ah, bl, bh;
                        unpk(cr[g][i], rl, rh);
                        unpk(cz[g][i], zl, zh);
                        unpk(cA[g][i], al, ah);
                        unpk(cB[g][i], bl, bh);
                        float mbr = g ? mb1r2.y : mb1r2.x;
                        float mbz = g ? mb1z2.y : mb1z2.x;
                        float bnA = g ? b1nA2.y : b1nA2.x;
                        float bnB = g ? b1nB2.y : b1nB2.x;
                        float sr = fmaf(tanhx((rl + rh) + mbr), 0.5f, 0.5f);
                        float sz = fmaf(tanhx((zl + zh) + mbz), 0.5f, 0.5f);
                        float xn = (al + ah) + bnA;
                        float hn = (bl + bh) + bnB;
                        float n = tanhx(fmaf(sr, hn, xn));
                        float hprev = g ? hp.y : hp.x;
                        o[g] = fmaf(sz, hprev - n, n);
                    }
                    *(float2*)(h1w + haddr(b, j0)) = make_float2(o[0], o[1]);
                }
            }
        }
        __syncthreads();
    }

    // ---- final projection: h0 final in buf[1] (+2048), h1 final in buf[1] ----
    if (tid < TILE_B) {
        int b = tid;
        const float* wps = smem + OFF_WP;
        const float* h0f = h0bs + 2048;
        const float* h1f = h1bs + 2048;
        float s = bp[0];
        #pragma unroll
        for (int c = 0; c < 16; ++c) {
            float4 h4 = *(const float4*)(h0f + hchunk(b, c));
            int k = c * 4;
            s = fmaf(h4.x, wps[k], s);
            s = fmaf(h4.y, wps[k + 1], s);
            s = fmaf(h4.z, wps[k + 2], s);
            s = fmaf(h4.w, wps[k + 3], s);
        }
        #pragma unroll
        for (int c = 0; c < 16; ++c) {
            float4 h4 = *(const float4*)(h1f + hchunk(b, c));
            int k = 64 + c * 4;
            s = fmaf(h4.x, wps[k], s);
            s = fmaf(h4.y, wps[k + 1], s);
            s = fmaf(h4.z, wps[k + 2], s);
            s = fmaf(h4.w, wps[k + 3], s);
        }
        out[b0 + tid] = s;
    }
}

extern "C" void kernel_launch(void* const* d_in, const int* in_sizes, int n_in,
                              void* d_out, int out_size) {
    const float* x    = (const float*)d_in[0];
    const float* Wih0 = (const float*)d_in[1];
    const float* Whh0 = (const float*)d_in[2];
    const float* bih0 = (const float*)d_in[3];
    const float* bhh0 = (const float*)d_in[4];
    const float* Wih1 = (const float*)d_in[5];
    const float* Whh1 = (const float*)d_in[6];
    const float* bih1 = (const float*)d_in[7];
    const float* bhh1 = (const float*)d_in[8];
    const float* Wp   = (const float*)d_in[9];
    const float* bp   = (const float*)d_in[10];
    float* out = (float*)d_out;

    cudaFuncSetAttribute(gru2_r8_kernel,
                         cudaFuncAttributeMaxDynamicSharedMemorySize, SMEM_BYTES);
    gru2_r8_kernel<<<NCTA, NTHREADS, SMEM_BYTES>>>(
        x, Wih0, Whh0, bih0, bhh0, Wih1, Whh1, bih1, bhh1, Wp, bp, out);
}

// round 10
// speedup vs baseline: 1.1595x; 1.0022x over previous
#include <cuda_runtime.h>

#define HID 64
#define GATES 192
#define BATCH 4096
#define TSTEPS 512
#define TILE_B 32
#define NCTA 128
#define NTHREADS 512

typedef unsigned long long ull;

// smem layout (float offsets)
#define OFF_W0   0        // Whh0 packed [k2][pair][blk][gi][kl] (12288)
#define OFF_WA   12288    // Wih1 packed
#define OFF_WB   24576    // Whh1 packed
#define OFF_H0   36864    // h0: 2 buffers x [32][64] swizzled
#define OFF_H1   40960    // h1: 2 buffers
#define OFF_WIH0 45056    // Wih0 col-major [2][192], r/z scaled 0.5
#define OFF_MB0  45440    // 0.5*(bih0+bhh0) r/z [128]
#define OFF_B0NX 45568
#define OFF_B0NH 45632
#define OFF_MB1  45696
#define OFF_B1NA 45824
#define OFF_B1NB 45888
#define OFF_WP   45952
#define OFF_XS   46080    // x staging float2[2][32]
#define SMEM_FLOATS 46208
#define SMEM_BYTES (SMEM_FLOATS * 4)   // 184832 B

__device__ __forceinline__ ull ffma2(ull a, ull b, ull c) {
    ull d; asm("fma.rn.f32x2 %0, %1, %2, %3;" : "=l"(d) : "l"(a), "l"(b), "l"(c)); return d;
}
__device__ __forceinline__ void unpk(ull v, float& lo, float& hi) {
    asm("mov.b64 {%0, %1}, %2;" : "=f"(lo), "=f"(hi) : "l"(v));
}
__device__ __forceinline__ float tanhx(float v) {
    float y; asm("tanh.approx.f32 %0, %1;" : "=f"(y) : "f"(v)); return y;
}
// swizzle: chunk index XORed with b>>2 (distinct across 8 lane-groups)
__device__ __forceinline__ int haddr(int b, int j) {
    return b * 64 + ((((j >> 2) ^ (b >> 2)) << 2) | (j & 3));
}
__device__ __forceinline__ int hchunk(int b, int c) {
    return b * 64 + (((c ^ (b >> 2)) & 15) << 2);
}

extern __shared__ float smem[];

__global__ void __launch_bounds__(NTHREADS, 1)
gru2_r8_kernel(const float* __restrict__ x,
               const float* __restrict__ Wih0, const float* __restrict__ Whh0,
               const float* __restrict__ bih0, const float* __restrict__ bhh0,
               const float* __restrict__ Wih1, const float* __restrict__ Whh1,
               const float* __restrict__ bih1, const float* __restrict__ bhh1,
               const float* __restrict__ Wp,   const float* __restrict__ bp,
               float* __restrict__ out)
{
    const int tid = threadIdx.x;
    const int b0  = blockIdx.x * TILE_B;

    float* w0s  = smem + OFF_W0;
    float* was  = smem + OFF_WA;
    float* wbs  = smem + OFF_WB;
    float* h0bs = smem + OFF_H0;
    float* h1bs = smem + OFF_H1;
    float* wih0s = smem + OFF_WIH0;
    float2* xsf = (float2*)(smem + OFF_XS);

    // ---- prologue: pack weights as {w_k, w_k+1} per gate, [k2][pair][blk] ----
    for (int d = tid; d < HID * GATES; d += NTHREADS) {
        int g = d >> 6, k = d & 63;        // source [192][64] row-major
        float s = (g < 128) ? 0.5f : 1.0f;
        int blk = g >> 6, j = g & 63;
        int fpos = (k >> 1) * 384 + (j >> 1) * 12 + blk * 4 + (j & 1) * 2 + (k & 1);
        w0s[fpos] = Whh0[d] * s;
        was[fpos] = Wih1[d] * s;
        wbs[fpos] = Whh1[d] * s;
    }
    for (int g = tid; g < GATES; g += NTHREADS) {
        float s = (g < 128) ? 0.5f : 1.0f;
        wih0s[g]         = Wih0[2 * g]     * s;
        wih0s[GATES + g] = Wih0[2 * g + 1] * s;
    }
    if (tid < 128) {
        smem[OFF_MB0 + tid] = 0.5f * (bih0[tid] + bhh0[tid]);
        smem[OFF_MB1 + tid] = 0.5f * (bih1[tid] + bhh1[tid]);
        smem[OFF_WP + tid]  = Wp[tid];
    }
    if (tid < 64) {
        smem[OFF_B0NX + tid] = bih0[128 + tid];
        smem[OFF_B0NH + tid] = bhh0[128 + tid];
        smem[OFF_B1NA + tid] = bih1[128 + tid];
        smem[OFF_B1NB + tid] = bhh1[128 + tid];
    }
    for (int d = tid; d < 8192; d += NTHREADS) h0bs[d] = 0.0f;   // h0 + h1, both buffers
    if (tid < TILE_B)
        xsf[tid] = *(const float2*)(x + (size_t)(b0 + tid) * 2);   // x(0) -> slot 0
    __syncthreads();

    // tiling within each 256-thread group: pair = gate-pair, bg = batch group of 4
    const int gtid = tid & 255;
    const int pair = gtid >> 3;         // 0..31
    const int bg   = gtid & 7;          // 0..7
    const int j0   = pair * 2;
    const int bb   = bg * 4;

    int rowb[4];
    #pragma unroll
    for (int i = 0; i < 4; ++i) rowb[i] = (bb + i) * 64;

    const float* wbase0 = w0s + pair * 12;
    const float* wbaseA = was + pair * 12;
    const float* wbaseB = wbs + pair * 12;

    // pipeline: iteration i -> group A does L0 step t=i, group B does L1 step t=i-1
    for (int it = 0; it <= TSTEPS; ++it) {
        if (tid < 256) {
            if (it < TSTEPS) {
                // ======== group A: GEMM1 (h0 @ Whh0^T) + gates L0, step t=it ========
                const float* h0r = h0bs + (((it + 1) & 1) << 11);
                float* h0w       = h0bs + ((it & 1) << 11);

                float2 xnext = make_float2(0.0f, 0.0f);
                if (gtid < TILE_B && it + 1 < TSTEPS)
                    xnext = *(const float2*)(x + ((size_t)(it + 1) * BATCH + b0 + gtid) * 2);

                ull ar[2][4], az[2][4], an[2][4];
                #pragma unroll
                for (int i = 0; i < 4; ++i) {
                    ar[0][i] = 0; ar[1][i] = 0; az[0][i] = 0;
                    az[1][i] = 0; an[0][i] = 0; an[1][i] = 0;
                }

                #pragma unroll 4
                for (int k4 = 0; k4 < 16; ++k4) {
                    const int coff = ((k4 ^ bg) << 2);
                    ulonglong2 h[4];
                    #pragma unroll
                    for (int i = 0; i < 4; ++i)
                        h[i] = *(const ulonglong2*)(h0r + rowb[i] + coff);
                    #pragma unroll
                    for (int kp = 0; kp < 2; ++kp) {
                        const float* w = wbase0 + (k4 * 2 + kp) * 384;
                        ulonglong2 wr = *(const ulonglong2*)(w);
                        ulonglong2 wz = *(const ulonglong2*)(w + 4);
                        ulonglong2 wn = *(const ulonglong2*)(w + 8);
                        #pragma unroll
                        for (int i = 0; i < 4; ++i) {
                            ull hv = kp ? h[i].y : h[i].x;
                            ar[0][i] = ffma2(wr.x, hv, ar[0][i]);
                            ar[1][i] = ffma2(wr.y, hv, ar[1][i]);
                            az[0][i] = ffma2(wz.x, hv, az[0][i]);
                            az[1][i] = ffma2(wz.y, hv, az[1][i]);
                            an[0][i] = ffma2(wn.x, hv, an[0][i]);
                            an[1][i] = ffma2(wn.y, hv, an[1][i]);
                        }
                    }
                }

                // constants reloaded per step (register relief at 512 threads)
                float2 mb0r2 = *(const float2*)(smem + OFF_MB0 + j0);
                float2 mb0z2 = *(const float2*)(smem + OFF_MB0 + 64 + j0);
                float2 b0nx2 = *(const float2*)(smem + OFF_B0NX + j0);
                float2 b0nh2 = *(const float2*)(smem + OFF_B0NH + j0);
                float2 xwr0 = *(const float2*)(wih0s + j0);
                float2 xwz0 = *(const float2*)(wih0s + 64 + j0);
                float2 xwn0 = *(const float2*)(wih0s + 128 + j0);
                float2 xwr1 = *(const float2*)(wih0s + GATES + j0);
                float2 xwz1 = *(const float2*)(wih0s + GATES + 64 + j0);
                float2 xwn1 = *(const float2*)(wih0s + GATES + 128 + j0);

                #pragma unroll
                for (int i = 0; i < 4; ++i) {
                    int b = bb + i;
                    float2 xv = xsf[(it & 1) * TILE_B + b];
                    float2 hp = *(const float2*)(h0r + haddr(b, j0));
                    float o[2];
                    #pragma unroll
                    for (int g = 0; g < 2; ++g) {
                        float rl, rh, zl, zh, nl, nh;
                        unpk(ar[g][i], rl, rh);
                        unpk(az[g][i], zl, zh);
                        unpk(an[g][i], nl, nh);
                        float mbr = g ? mb0r2.y : mb0r2.x;
                        float mbz = g ? mb0z2.y : mb0z2.x;
                        float bnx = g ? b0nx2.y : b0nx2.x;
                        float bnh = g ? b0nh2.y : b0nh2.x;
                        float wr0 = g ? xwr0.y : xwr0.x, wr1 = g ? xwr1.y : xwr1.x;
                        float wz0 = g ? xwz0.y : xwz0.x, wz1 = g ? xwz1.y : xwz1.x;
                        float wn0 = g ? xwn0.y : xwn0.x, wn1 = g ? xwn1.y : xwn1.x;
                        float rsum = fmaf(xv.y, wr1, fmaf(xv.x, wr0, (rl + rh) + mbr));
                        float zsum = fmaf(xv.y, wz1, fmaf(xv.x, wz0, (zl + zh) + mbz));
                        float sr = fmaf(tanhx(rsum), 0.5f, 0.5f);
                        float sz = fmaf(tanhx(zsum), 0.5f, 0.5f);
                        float hn = (nl + nh) + bnh;
                        float xn = fmaf(xv.y, wn1, fmaf(xv.x, wn0, bnx));
                        float n = tanhx(fmaf(sr, hn, xn));
                        float hprev = g ? hp.y : hp.x;
                        o[g] = fmaf(sz, hprev - n, n);
                    }
                    *(float2*)(h0w + haddr(b, j0)) = make_float2(o[0], o[1]);
                }

                if (gtid < TILE_B)
                    xsf[((it + 1) & 1) * TILE_B + gtid] = xnext;
            }
        } else {
            if (it >= 1) {
                // ======== group B: GEMM2 (h0@Wih1 + h1@Whh1) + gates L1, step t=it-1 ========
                const float* hAr = h0bs + (((it - 1) & 1) << 11);   // h0 after t=it-1
                const float* h1r = h1bs + ((it & 1) << 11);         // h1 after t=it-2
                float* h1w       = h1bs + (((it - 1) & 1) << 11);

                ull cr[2][4], cz[2][4], cA[2][4], cB[2][4];
                #pragma unroll
                for (int i = 0; i < 4; ++i) {
                    cr[0][i] = 0; cr[1][i] = 0; cz[0][i] = 0; cz[1][i] = 0;
                    cA[0][i] = 0; cA[1][i] = 0; cB[0][i] = 0; cB[1][i] = 0;
                }

                #pragma unroll 2
                for (int k4 = 0; k4 < 16; ++k4) {
                    const int coff = ((k4 ^ bg) << 2);
                    ulonglong2 hA[4], hB[4];
                    #pragma unroll
                    for (int i = 0; i < 4; ++i) {
                        int off = rowb[i] + coff;
                        hA[i] = *(const ulonglong2*)(hAr + off);
                        hB[i] = *(const ulonglong2*)(h1r + off);
                    }
                    #pragma unroll
                    for (int kp = 0; kp < 2; ++kp) {
                        int woff = (k4 * 2 + kp) * 384;
                        const float* wa = wbaseA + woff;
                        const float* wb = wbaseB + woff;
                        ulonglong2 war = *(const ulonglong2*)(wa);
                        ulonglong2 waz = *(const ulonglong2*)(wa + 4);
                        ulonglong2 wan = *(const ulonglong2*)(wa + 8);
                        ulonglong2 wbr = *(const ulonglong2*)(wb);
                        ulonglong2 wbz = *(const ulonglong2*)(wb + 4);
                        ulonglong2 wbn = *(const ulonglong2*)(wb + 8);
                        #pragma unroll
                        for (int i = 0; i < 4; ++i) {
                            ull av = kp ? hA[i].y : hA[i].x;
                            ull bv = kp ? hB[i].y : hB[i].x;
                            cr[0][i] = ffma2(war.x, av, cr[0][i]);
                            cr[0][i] = ffma2(wbr.x, bv, cr[0][i]);
                            cr[1][i] = ffma2(war.y, av, cr[1][i]);
                            cr[1][i] = ffma2(wbr.y, bv, cr[1][i]);
                            cz[0][i] = ffma2(waz.x, av, cz[0][i]);
                            cz[0][i] = ffma2(wbz.x, bv, cz[0][i]);
                            cz[1][i] = ffma2(waz.y, av, cz[1][i]);
                            cz[1][i] = ffma2(wbz.y, bv, cz[1][i]);
                            cA[0][i] = ffma2(wan.x, av, cA[0][i]);
                            cA[1][i] = ffma2(wan.y, av, cA[1][i]);
                            cB[0][i] = ffma2(wbn.x, bv, cB[0][i]);
                            cB[1][i] = ffma2(wbn.y, bv, cB[1][i]);
                        }
                    }
                }

                float2 mb1r2 = *(const float2*)(smem + OFF_MB1 + j0);
                float2 mb1z2 = *(const float2*)(smem + OFF_MB1 + 64 + j0);
                float2 b1nA2 = *(const float2*)(smem + OFF_B1NA + j0);
                float2 b1nB2 = *(const float2*)(smem + OFF_B1NB + j0);

                #pragma unroll
                for (int i = 0; i < 4; ++i) {
                    int b = bb + i;
                    float2 hp = *(const float2*)(h1r + haddr(b, j0));
                    float o[2];
                    #pragma unroll
                    for (int g = 0; g < 2; ++g) {
                        float rl, rh, zl, zh, al, ah, bl, bh;
                        unpk(cr[g][i], rl, rh);
                        unpk(cz[g][i], zl, zh);
                        unpk(cA[g][i], al, ah);
                        unpk(cB[g][i], bl, bh);
                        float mbr = g ? mb1r2.y : mb1r2.x;
                        float mbz = g ? mb1z2.y : mb1z2.x;
                        float bnA = g ? b1nA2.y : b1nA2.x;
                        float bnB = g ? b1nB2.y : b1nB2.x;
                        float sr = fmaf(tanhx((rl + rh) + mbr), 0.5f, 0.5f);
                        float sz = fmaf(tanhx((zl + zh) + mbz), 0.5f, 0.5f);
                        float xn = (al + ah) + bnA;
                        float hn = (bl + bh) + bnB;
                        float n = tanhx(fmaf(sr, hn, xn));
                        float hprev = g ? hp.y : hp.x;
                        o[g] = fmaf(sz, hprev - n, n);
                    }
                    *(float2*)(h1w + haddr(b, j0)) = make_float2(o[0], o[1]);
                }
            }
        }
        __syncthreads();
    }

    // ---- final projection: h0 final in buf[1] (+2048), h1 final in buf[1] ----
    if (tid < TILE_B) {
        int b = tid;
        const float* wps = smem + OFF_WP;
        const float* h0f = h0bs + 2048;
        const float* h1f = h1bs + 2048;
        float s = bp[0];
        #pragma unroll
        for (int c = 0; c < 16; ++c) {
            float4 h4 = *(const float4*)(h0f + hchunk(b, c));
            int k = c * 4;
            s = fmaf(h4.x, wps[k], s);
            s = fmaf(h4.y, wps[k + 1], s);
            s = fmaf(h4.z, wps[k + 2], s);
            s = fmaf(h4.w, wps[k + 3], s);
        }
        #pragma unroll
        for (int c = 0; c < 16; ++c) {
            float4 h4 = *(const float4*)(h1f + hchunk(b, c));
            int k = 64 + c * 4;
            s = fmaf(h4.x, wps[k], s);
            s = fmaf(h4.y, wps[k + 1], s);
            s = fmaf(h4.z, wps[k + 2], s);
            s = fmaf(h4.w, wps[k + 3], s);
        }
        out[b0 + tid] = s;
    }
}

extern "C" void kernel_launch(void* const* d_in, const int* in_sizes, int n_in,
                              void* d_out, int out_size) {
    const float* x    = (const float*)d_in[0];
    const float* Wih0 = (const float*)d_in[1];
    const float* Whh0 = (const float*)d_in[2];
    const float* bih0 = (const float*)d_in[3];
    const float* bhh0 = (const float*)d_in[4];
    const float* Wih1 = (const float*)d_in[5];
    const float* Whh1 = (const float*)d_in[6];
    const float* bih1 = (const float*)d_in[7];
    const float* bhh1 = (const float*)d_in[8];
    const float* Wp   = (const float*)d_in[9];
    const float* bp   = (const float*)d_in[10];
    float* out = (float*)d_out;

    cudaFuncSetAttribute(gru2_r8_kernel,
                         cudaFuncAttributeMaxDynamicSharedMemorySize, SMEM_BYTES);
    gru2_r8_kernel<<<NCTA, NTHREADS, SMEM_BYTES>>>(
        x, Wih0, Whh0, bih0, bhh0, Wih1, Whh1, bih1, bhh1, Wp, bp, out);
}